// round 3
// baseline (speedup 1.0000x reference)
#include <cuda_runtime.h>

// Problem constants (fixed by the reference):
//   N=4096 samples, D=128 input dim, P=128 pe dim (== D), H=256 hidden.
#define NN 4096
#define DD 128
#define HH 256

// Scratch: base[n][h] = (x @ W1[:D])[n][h] + b1[h]
__device__ float g_base[NN * HH];

typedef unsigned long long u64;

__device__ __forceinline__ u64 pk2(float x, float y) {
    u64 r; asm("mov.b64 %0, {%1, %2};" : "=l"(r) : "f"(x), "f"(y)); return r;
}
__device__ __forceinline__ u64 fma2_(u64 a, u64 b, u64 c) {
    u64 d; asm("fma.rn.f32x2 %0, %1, %2, %3;" : "=l"(d) : "l"(a), "l"(b), "l"(c)); return d;
}
__device__ __forceinline__ u64 add2_(u64 a, u64 b) {
    u64 d; asm("add.rn.f32x2 %0, %1, %2;" : "=l"(d) : "l"(a), "l"(b)); return d;
}
__device__ __forceinline__ u64 relu2_(u64 a) {
    float x, y;
    asm("mov.b64 {%0, %1}, %2;" : "=f"(x), "=f"(y) : "l"(a));
    x = fmaxf(x, 0.0f); y = fmaxf(y, 0.0f);
    return pk2(x, y);
}
__device__ __forceinline__ float2 unpk(u64 a) {
    float2 v; asm("mov.b64 {%0, %1}, %2;" : "=f"(v.x), "=f"(v.y) : "l"(a)); return v;
}

// ---------------------------------------------------------------------------
// K1: base = x @ W1[:D] + b1   (4096 x 256, K=128), f32x2 accumulators.
// Tiles: 64(n) x 64(h) x 32(k); 256 threads; microtile 4n x 4h (2 packed).
// Also writes the leading ones column of the output (blockIdx.y == 0).
// ---------------------------------------------------------------------------
__global__ __launch_bounds__(256) void nimo_base_kernel(
    const float* __restrict__ x, const float* __restrict__ W1,
    const float* __restrict__ b1, float* __restrict__ out)
{
    __shared__ __align__(16) float xs[32][68];  // [k][n] transposed, padded
    __shared__ __align__(16) float ws[32][68];  // [k][h], padded

    const int tid = threadIdx.x;
    const int n0 = blockIdx.x * 64;
    const int h0 = blockIdx.y * 64;
    const int tx = tid & 15;   // h group -> 4 h (2 packed pairs)
    const int ty = tid >> 4;   // n group -> 4 n

    u64 acc[4][2];
#pragma unroll
    for (int i = 0; i < 4; i++) { acc[i][0] = 0ull; acc[i][1] = 0ull; }

    for (int kt = 0; kt < DD; kt += 32) {
#pragma unroll
        for (int i = 0; i < 8; i++) {           // 64n x 32k
            int e = tid + i * 256;
            int r = e >> 5, k = e & 31;
            xs[k][r] = x[(n0 + r) * DD + kt + k];
        }
#pragma unroll
        for (int i = 0; i < 8; i++) {           // 32k x 64h
            int e = tid + i * 256;
            int k = e >> 6, c = e & 63;
            ws[k][c] = W1[(kt + k) * HH + h0 + c];
        }
        __syncthreads();
#pragma unroll
        for (int kk = 0; kk < 32; kk++) {
            float4 xv = *(const float4*)&xs[kk][ty * 4];
            float4 wv = *(const float4*)&ws[kk][tx * 4];
            u64 wa = pk2(wv.x, wv.y), wb = pk2(wv.z, wv.w);
            u64 x0 = pk2(xv.x, xv.x), x1 = pk2(xv.y, xv.y);
            u64 x2 = pk2(xv.z, xv.z), x3 = pk2(xv.w, xv.w);
            acc[0][0] = fma2_(x0, wa, acc[0][0]); acc[0][1] = fma2_(x0, wb, acc[0][1]);
            acc[1][0] = fma2_(x1, wa, acc[1][0]); acc[1][1] = fma2_(x1, wb, acc[1][1]);
            acc[2][0] = fma2_(x2, wa, acc[2][0]); acc[2][1] = fma2_(x2, wb, acc[2][1]);
            acc[3][0] = fma2_(x3, wa, acc[3][0]); acc[3][1] = fma2_(x3, wb, acc[3][1]);
        }
        __syncthreads();
    }

    float4 bv = *(const float4*)&b1[h0 + tx * 4];
    u64 ba = pk2(bv.x, bv.y), bb = pk2(bv.z, bv.w);
#pragma unroll
    for (int i = 0; i < 4; i++) {
        float2 oa = unpk(add2_(acc[i][0], ba));
        float2 ob = unpk(add2_(acc[i][1], bb));
        float4 o = make_float4(oa.x, oa.y, ob.x, ob.y);
        *(float4*)&g_base[(n0 + ty * 4 + i) * HH + h0 + tx * 4] = o;
    }

    // ones column
    if (blockIdx.y == 0 && tid < 64) out[(n0 + tid) * (DD + 1)] = 1.0f;
}

// ---------------------------------------------------------------------------
// K2: per (n, j):
//   g = sum_h relu(base[n,h] + W1[D+j,h] - x[n,j]*W1[j,h]) * W2[h]
//   out[n, 1+j] = x[n,j] * (1 + b2 + g)
//
// Lane layout: nl = lane&1 -> one of 2 j per warp; hg = lane>>1 -> 16-h
// segment. W1[j], pe[j] = W1[D+j], W2 segments live in REGISTERS for the
// whole n-loop (loaded once). Per n: 4 LDG.128 of base (2-way dup; shared
// across all 8 warps -> L1 hits) + 1 LDG of x. Reduction over hg = 4 shfl.
// Block = 8 warps = 16 j; grid = (64 n-tiles of 64) x (8 j-tiles of 16).
// ---------------------------------------------------------------------------
__global__ __launch_bounds__(256, 2) void nimo_main_kernel(
    const float* __restrict__ x, const float* __restrict__ W1,
    const float* __restrict__ W2, const float* __restrict__ b2,
    float* __restrict__ out)
{
    const int tid  = threadIdx.x;
    const int lane = tid & 31;
    const int warp = tid >> 5;
    const int nl   = lane & 1;    // j within warp
    const int hg   = lane >> 1;   // h-segment (16 h)
    const int n0   = blockIdx.x * 64;
    const int j0   = blockIdx.y * 16;
    const int j    = j0 + warp * 2 + nl;
    const int hseg = hg * 16;

    // ---- persistent registers: W1[j] seg, pe[j] seg, W2 seg ----
    u64 w1p[8], pep[8], w2p[8];
    {
        const float4* w1r = (const float4*)&W1[j * HH + hseg];
        const float4* per = (const float4*)&W1[(DD + j) * HH + hseg];
        const float4* w2r = (const float4*)&W2[hseg];
#pragma unroll
        for (int c = 0; c < 4; c++) {
            float4 a = w1r[c], p = per[c], w = w2r[c];
            w1p[2 * c] = pk2(a.x, a.y); w1p[2 * c + 1] = pk2(a.z, a.w);
            pep[2 * c] = pk2(p.x, p.y); pep[2 * c + 1] = pk2(p.z, p.w);
            w2p[2 * c] = pk2(w.x, w.y); w2p[2 * c + 1] = pk2(w.z, w.w);
        }
    }
    const float ob2 = 1.0f + b2[0];

#pragma unroll 2
    for (int ni = 0; ni < 64; ni++) {
        const int n = n0 + ni;
        const float xj = __ldg(&x[n * DD + j]);
        const u64 nx2 = pk2(-xj, -xj);
        const float4* br = (const float4*)&g_base[n * HH + hseg];
        u64 acc0 = 0ull, acc1 = 0ull;
#pragma unroll
        for (int c = 0; c < 4; c++) {
            float4 bv = br[c];
            u64 b0 = pk2(bv.x, bv.y), b1v = pk2(bv.z, bv.w);
            u64 v0 = relu2_(add2_(fma2_(nx2, w1p[2 * c],     pep[2 * c]),     b0));
            u64 v1 = relu2_(add2_(fma2_(nx2, w1p[2 * c + 1], pep[2 * c + 1]), b1v));
            acc0 = fma2_(v0, w2p[2 * c], acc0);
            acc1 = fma2_(v1, w2p[2 * c + 1], acc1);
        }
        float2 a = unpk(add2_(acc0, acc1));
        float s = a.x + a.y;
        s += __shfl_xor_sync(0xffffffffu, s, 2);
        s += __shfl_xor_sync(0xffffffffu, s, 4);
        s += __shfl_xor_sync(0xffffffffu, s, 8);
        s += __shfl_xor_sync(0xffffffffu, s, 16);
        if (hg == 0) out[n * (DD + 1) + 1 + j] = xj * (ob2 + s);
    }
}

extern "C" void kernel_launch(void* const* d_in, const int* in_sizes, int n_in,
                              void* d_out, int out_size)
{
    const float* x  = (const float*)d_in[0];
    const float* W1 = (const float*)d_in[1];
    const float* b1 = (const float*)d_in[2];
    const float* W2 = (const float*)d_in[3];
    const float* b2 = (const float*)d_in[4];
    float* out = (float*)d_out;

    // K1: base GEMM + ones column. grid: 64 n-tiles x 4 h-tiles.
    nimo_base_kernel<<<dim3(64, 4), 256>>>(x, W1, b1, out);
    // K2: masked-MLP evaluation. grid: 64 n-tiles x 8 j-tiles.
    nimo_main_kernel<<<dim3(64, 8), 256>>>(x, W1, W2, b2, out);
}

// round 4
// speedup vs baseline: 1.0597x; 1.0597x over previous
#include <cuda_runtime.h>

// Problem constants (fixed by the reference):
//   N=4096 samples, D=128 input dim, P=128 pe dim (== D), H=256 hidden.
#define NN 4096
#define DD 128
#define HH 256
#define NCH 16   // n per chunk in K2
#define NPB 128  // n per block in K2

// Scratch: base[n][h] = (x @ W1[:D])[n][h] + b1[h]
__device__ float g_base[NN * HH];

typedef unsigned long long u64;

__device__ __forceinline__ u64 pk2(float x, float y) {
    u64 r; asm("mov.b64 %0, {%1, %2};" : "=l"(r) : "f"(x), "f"(y)); return r;
}
__device__ __forceinline__ u64 fma2_(u64 a, u64 b, u64 c) {
    u64 d; asm("fma.rn.f32x2 %0, %1, %2, %3;" : "=l"(d) : "l"(a), "l"(b), "l"(c)); return d;
}
__device__ __forceinline__ u64 add2_(u64 a, u64 b) {
    u64 d; asm("add.rn.f32x2 %0, %1, %2;" : "=l"(d) : "l"(a), "l"(b)); return d;
}
__device__ __forceinline__ u64 relu2_(u64 a) {
    float x, y;
    asm("mov.b64 {%0, %1}, %2;" : "=f"(x), "=f"(y) : "l"(a));
    x = fmaxf(x, 0.0f); y = fmaxf(y, 0.0f);
    return pk2(x, y);
}
__device__ __forceinline__ float2 unpk(u64 a) {
    float2 v; asm("mov.b64 {%0, %1}, %2;" : "=f"(v.x), "=f"(v.y) : "l"(a)); return v;
}

// ---------------------------------------------------------------------------
// K1: base = x @ W1[:D] + b1   (4096 x 256, K=128), f32x2 accumulators.
// Tiles: 64(n) x 64(h) x 32(k); 256 threads; microtile 4n x 4h (2 packed).
// Also writes the leading ones column of the output (blockIdx.y == 0).
// ---------------------------------------------------------------------------
__global__ __launch_bounds__(256) void nimo_base_kernel(
    const float* __restrict__ x, const float* __restrict__ W1,
    const float* __restrict__ b1, float* __restrict__ out)
{
    __shared__ __align__(16) float xs[32][68];  // [k][n] transposed, padded
    __shared__ __align__(16) float ws[32][68];  // [k][h], padded

    const int tid = threadIdx.x;
    const int n0 = blockIdx.x * 64;
    const int h0 = blockIdx.y * 64;
    const int tx = tid & 15;   // h group -> 4 h (2 packed pairs)
    const int ty = tid >> 4;   // n group -> 4 n

    u64 acc[4][2];
#pragma unroll
    for (int i = 0; i < 4; i++) { acc[i][0] = 0ull; acc[i][1] = 0ull; }

    for (int kt = 0; kt < DD; kt += 32) {
#pragma unroll
        for (int i = 0; i < 8; i++) {           // 64n x 32k
            int e = tid + i * 256;
            int r = e >> 5, k = e & 31;
            xs[k][r] = x[(n0 + r) * DD + kt + k];
        }
#pragma unroll
        for (int i = 0; i < 8; i++) {           // 32k x 64h
            int e = tid + i * 256;
            int k = e >> 6, c = e & 63;
            ws[k][c] = W1[(kt + k) * HH + h0 + c];
        }
        __syncthreads();
#pragma unroll
        for (int kk = 0; kk < 32; kk++) {
            float4 xv = *(const float4*)&xs[kk][ty * 4];
            float4 wv = *(const float4*)&ws[kk][tx * 4];
            u64 wa = pk2(wv.x, wv.y), wb = pk2(wv.z, wv.w);
            u64 x0 = pk2(xv.x, xv.x), x1 = pk2(xv.y, xv.y);
            u64 x2 = pk2(xv.z, xv.z), x3 = pk2(xv.w, xv.w);
            acc[0][0] = fma2_(x0, wa, acc[0][0]); acc[0][1] = fma2_(x0, wb, acc[0][1]);
            acc[1][0] = fma2_(x1, wa, acc[1][0]); acc[1][1] = fma2_(x1, wb, acc[1][1]);
            acc[2][0] = fma2_(x2, wa, acc[2][0]); acc[2][1] = fma2_(x2, wb, acc[2][1]);
            acc[3][0] = fma2_(x3, wa, acc[3][0]); acc[3][1] = fma2_(x3, wb, acc[3][1]);
        }
        __syncthreads();
    }

    float4 bv = *(const float4*)&b1[h0 + tx * 4];
    u64 ba = pk2(bv.x, bv.y), bb = pk2(bv.z, bv.w);
#pragma unroll
    for (int i = 0; i < 4; i++) {
        float2 oa = unpk(add2_(acc[i][0], ba));
        float2 ob = unpk(add2_(acc[i][1], bb));
        float4 o = make_float4(oa.x, oa.y, ob.x, ob.y);
        *(float4*)&g_base[(n0 + ty * 4 + i) * HH + h0 + tx * 4] = o;
    }

    // ones column
    if (blockIdx.y == 0 && tid < 64) out[(n0 + tid) * (DD + 1)] = 1.0f;
}

// ---------------------------------------------------------------------------
// K2: per (n, j):
//   g = sum_h relu(base[n,h] + W1[D+j,h] - x[n,j]*W1[j,h]) * W2[h]
//   out[n, 1+j] = x[n,j] * (1 + b2 + g)
//
// Lane <-> j (32 j per warp). Warp <-> 16-h segment (16 warps cover H=256).
// Per lane, register-persistent for the whole kernel: W1[j,seg], pe[j,seg]
// (= W1[D+j,seg]), W2[seg]. Per n: base[n,seg] via 4 lane-uniform LDG.128
// (1 wavefront each, L1-hot) + 1 coalesced x load. The h-dot is fully
// intra-lane (no shuffles). Cross-warp (16-way) h-reduction is batched per
// 16-n chunk through smem with conflict-free STS/LDS and coalesced output.
// Block = 512 threads (16 warps); grid = (32 n-blocks of 128) x (4 j-tiles).
// ---------------------------------------------------------------------------
__global__ __launch_bounds__(512) void nimo_main_kernel(
    const float* __restrict__ x, const float* __restrict__ W1,
    const float* __restrict__ W2, const float* __restrict__ b2,
    float* __restrict__ out)
{
    __shared__ float red[16 * NCH * 32];  // [warp][n'][j'] = 32 KB

    const int tid  = threadIdx.x;
    const int lane = tid & 31;
    const int warp = tid >> 5;
    const int n0   = blockIdx.x * NPB;
    const int j0   = blockIdx.y * 32;
    const int j    = j0 + lane;
    const int hseg = warp * 16;

    // ---- persistent registers: W1[j,seg], pe[j,seg], W2[seg] (8 packed each)
    u64 w1p[8], pep[8], w2p[8];
    {
        const float4* w1r = (const float4*)&W1[j * HH + hseg];
        const float4* per = (const float4*)&W1[(DD + j) * HH + hseg];
        const float4* w2r = (const float4*)&W2[hseg];
#pragma unroll
        for (int c = 0; c < 4; c++) {
            float4 a = w1r[c], p = per[c], w = w2r[c];
            w1p[2 * c] = pk2(a.x, a.y); w1p[2 * c + 1] = pk2(a.z, a.w);
            pep[2 * c] = pk2(p.x, p.y); pep[2 * c + 1] = pk2(p.z, p.w);
            w2p[2 * c] = pk2(w.x, w.y); w2p[2 * c + 1] = pk2(w.z, w.w);
        }
    }
    const float ob2 = 1.0f + b2[0];

    for (int ch = 0; ch < NPB; ch += NCH) {
        float accs[NCH];
#pragma unroll
        for (int ni = 0; ni < NCH; ni++) {
            const int n = n0 + ch + ni;
            const float xj = __ldg(&x[n * DD + j]);        // coalesced
            const u64 nx2 = pk2(-xj, -xj);
            const float4* br = (const float4*)&g_base[n * HH + hseg];  // lane-uniform
            u64 a0 = 0ull, a1 = 0ull;
#pragma unroll
            for (int c = 0; c < 4; c++) {
                float4 bv = br[c];
                u64 b0 = pk2(bv.x, bv.y), b1v = pk2(bv.z, bv.w);
                u64 v0 = relu2_(add2_(fma2_(nx2, w1p[2 * c],     pep[2 * c]),     b0));
                u64 v1 = relu2_(add2_(fma2_(nx2, w1p[2 * c + 1], pep[2 * c + 1]), b1v));
                a0 = fma2_(v0, w2p[2 * c], a0);
                a1 = fma2_(v1, w2p[2 * c + 1], a1);
            }
            float2 t = unpk(add2_(a0, a1));
            accs[ni] = t.x + t.y;
        }
        // ---- stage partials: red[warp][ni][lane]
#pragma unroll
        for (int ni = 0; ni < NCH; ni++)
            red[warp * (NCH * 32) + ni * 32 + lane] = accs[ni];
        __syncthreads();
        // ---- 16-way reduce + output: thread t -> (n' = t>>5, j' = t&31)
        {
            const int nn = tid >> 5;    // 0..15
            const int jj = tid & 31;
            float s = 0.0f;
#pragma unroll
            for (int w = 0; w < 16; w++)
                s += red[w * (NCH * 32) + nn * 32 + jj];
            const int n = n0 + ch + nn;
            const float xj = x[n * DD + j0 + jj];
            out[n * (DD + 1) + 1 + j0 + jj] = xj * (ob2 + s);
        }
        __syncthreads();
    }
}

extern "C" void kernel_launch(void* const* d_in, const int* in_sizes, int n_in,
                              void* d_out, int out_size)
{
    const float* x  = (const float*)d_in[0];
    const float* W1 = (const float*)d_in[1];
    const float* b1 = (const float*)d_in[2];
    const float* W2 = (const float*)d_in[3];
    const float* b2 = (const float*)d_in[4];
    float* out = (float*)d_out;

    // K1: base GEMM + ones column. grid: 64 n-tiles x 4 h-tiles.
    nimo_base_kernel<<<dim3(64, 4), 256>>>(x, W1, b1, out);
    // K2: masked-MLP evaluation. grid: 32 n-blocks x 4 j-tiles, 512 threads.
    nimo_main_kernel<<<dim3(32, 4), 512>>>(x, W1, W2, b2, out);
}

// round 5
// speedup vs baseline: 1.3423x; 1.2667x over previous
#include <cuda_runtime.h>

// Problem constants (fixed by the reference):
//   N=4096 samples, D=128 input dim, P=128 pe dim (== D), H=256 hidden.
#define NN 4096
#define DD 128
#define HH 256
#define JT 16   // j per block in K2

// Scratch: base[n][h] = (x @ W1[:D])[n][h] + b1[h]
__device__ float g_base[NN * HH];

typedef unsigned long long u64;

__device__ __forceinline__ u64 pk2(float x, float y) {
    u64 r; asm("mov.b64 %0, {%1, %2};" : "=l"(r) : "f"(x), "f"(y)); return r;
}
__device__ __forceinline__ u64 fma2_(u64 a, u64 b, u64 c) {
    u64 d; asm("fma.rn.f32x2 %0, %1, %2, %3;" : "=l"(d) : "l"(a), "l"(b), "l"(c)); return d;
}
__device__ __forceinline__ u64 add2_(u64 a, u64 b) {
    u64 d; asm("add.rn.f32x2 %0, %1, %2;" : "=l"(d) : "l"(a), "l"(b)); return d;
}
__device__ __forceinline__ u64 relu2_(u64 a) {
    float x, y;
    asm("mov.b64 {%0, %1}, %2;" : "=f"(x), "=f"(y) : "l"(a));
    x = fmaxf(x, 0.0f); y = fmaxf(y, 0.0f);
    return pk2(x, y);
}
__device__ __forceinline__ float2 unpk(u64 a) {
    float2 v; asm("mov.b64 {%0, %1}, %2;" : "=f"(v.x), "=f"(v.y) : "l"(a)); return v;
}

// ---------------------------------------------------------------------------
// K1: base = x @ W1[:D] + b1   (4096 x 256, K=128), f32x2 accumulators.
// Tiles: 64(n) x 64(h) x 32(k); 256 threads; microtile 4n x 4h (2 packed).
// Also writes the leading ones column of the output (blockIdx.y == 0).
// ---------------------------------------------------------------------------
__global__ __launch_bounds__(256) void nimo_base_kernel(
    const float* __restrict__ x, const float* __restrict__ W1,
    const float* __restrict__ b1, float* __restrict__ out)
{
    __shared__ __align__(16) float xs[32][68];  // [k][n] transposed, padded
    __shared__ __align__(16) float ws[32][68];  // [k][h], padded

    const int tid = threadIdx.x;
    const int n0 = blockIdx.x * 64;
    const int h0 = blockIdx.y * 64;
    const int tx = tid & 15;   // h group -> 4 h (2 packed pairs)
    const int ty = tid >> 4;   // n group -> 4 n

    u64 acc[4][2];
#pragma unroll
    for (int i = 0; i < 4; i++) { acc[i][0] = 0ull; acc[i][1] = 0ull; }

    for (int kt = 0; kt < DD; kt += 32) {
#pragma unroll
        for (int i = 0; i < 8; i++) {           // 64n x 32k
            int e = tid + i * 256;
            int r = e >> 5, k = e & 31;
            xs[k][r] = x[(n0 + r) * DD + kt + k];
        }
#pragma unroll
        for (int i = 0; i < 8; i++) {           // 32k x 64h
            int e = tid + i * 256;
            int k = e >> 6, c = e & 63;
            ws[k][c] = W1[(kt + k) * HH + h0 + c];
        }
        __syncthreads();
#pragma unroll
        for (int kk = 0; kk < 32; kk++) {
            float4 xv = *(const float4*)&xs[kk][ty * 4];
            float4 wv = *(const float4*)&ws[kk][tx * 4];
            u64 wa = pk2(wv.x, wv.y), wb = pk2(wv.z, wv.w);
            u64 x0 = pk2(xv.x, xv.x), x1 = pk2(xv.y, xv.y);
            u64 x2 = pk2(xv.z, xv.z), x3 = pk2(xv.w, xv.w);
            acc[0][0] = fma2_(x0, wa, acc[0][0]); acc[0][1] = fma2_(x0, wb, acc[0][1]);
            acc[1][0] = fma2_(x1, wa, acc[1][0]); acc[1][1] = fma2_(x1, wb, acc[1][1]);
            acc[2][0] = fma2_(x2, wa, acc[2][0]); acc[2][1] = fma2_(x2, wb, acc[2][1]);
            acc[3][0] = fma2_(x3, wa, acc[3][0]); acc[3][1] = fma2_(x3, wb, acc[3][1]);
        }
        __syncthreads();
    }

    float4 bv = *(const float4*)&b1[h0 + tx * 4];
    u64 ba = pk2(bv.x, bv.y), bb = pk2(bv.z, bv.w);
#pragma unroll
    for (int i = 0; i < 4; i++) {
        float2 oa = unpk(add2_(acc[i][0], ba));
        float2 ob = unpk(add2_(acc[i][1], bb));
        float4 o = make_float4(oa.x, oa.y, ob.x, ob.y);
        *(float4*)&g_base[(n0 + ty * 4 + i) * HH + h0 + tx * 4] = o;
    }

    // ones column
    if (blockIdx.y == 0 && tid < 64) out[(n0 + tid) * (DD + 1)] = 1.0f;
}

// ---------------------------------------------------------------------------
// K2: per (n, j):
//   g = sum_h relu(base[n,h] + W1[D+j,h] - x[n,j]*W1[j,h]) * W2[h]
//   out[n, 1+j] = x[n,j] * (1 + b2 + g)
//
// Warp layout: lane = hg*4 + nl; hg in [0,8) owns h-segment [hg*32, hg*32+32),
// nl in [0,4) owns one n (n = n0 + warp*4 + nl). base (32 h) and W2 segments
// live in REGISTERS for the whole j-loop. W1/pe rows for the block's JT=16
// j's are staged in smem in a chunk-transposed layout: 16B chunk (row, hg, c)
// sits at row*1024 + c*128 + hg*16 bytes. Inner-loop LDS.128 therefore has
// per-instruction addresses = 8 contiguous 16B chunks (conflict-free, 1 wf,
// broadcast over nl) AND affine-in-c addressing (immediate offsets, zero
// per-load address math). Staging uses the self-inverse chunk bit-swap
// q = (d&7)*8 + (d>>3) so STS is conflict-free too.
// Reduction over hg = 3 shfl_xor covering 4 n at once.
// Block = 256 thr (8 warps, 32 n); grid = (128 n-tiles) x (8 j-tiles).
// ---------------------------------------------------------------------------
__global__ __launch_bounds__(256, 2) void nimo_main_kernel(
    const float* __restrict__ x, const float* __restrict__ W1,
    const float* __restrict__ W2, const float* __restrict__ b2,
    float* __restrict__ out)
{
    __shared__ __align__(16) float ws[2 * JT * HH];  // 32 KB, row 2r = W1[j0+r], 2r+1 = W1[D+j0+r]
    __shared__ float xs[JT][32];                     // 2 KB

    const int tid  = threadIdx.x;
    const int lane = tid & 31;
    const int warp = tid >> 5;
    const int nl   = lane & 3;
    const int hg   = lane >> 2;
    const int n0   = blockIdx.x * 32;
    const int j0   = blockIdx.y * JT;
    const int n    = n0 + warp * 4 + nl;

    // ---- stage W1/pe rows, chunk-transposed ----
    for (int row = warp; row < 2 * JT; row += 8) {
        int r = row >> 1;
        int src = (row & 1) ? (DD + j0 + r) : (j0 + r);
#pragma unroll
        for (int pass = 0; pass < 2; pass++) {
            int d = lane + pass * 32;              // dst chunk (conflict-free STS)
            int q = ((d & 7) << 3) | (d >> 3);     // src chunk (bit-swap)
            float4 v = *(const float4*)&W1[src * HH + q * 4];
            *(float4*)&ws[row * HH + d * 4] = v;
        }
    }
    // ---- stage x tile: xs[j'][n'] ----
#pragma unroll
    for (int p = 0; p < JT / 8; p++) {
        int jj = (tid >> 5) + p * 8;
        int nn = tid & 31;
        xs[jj][nn] = x[(n0 + nn) * DD + j0 + jj];
    }

    // ---- persistent registers: base[n, hg-seg] and W2[hg-seg], packed ----
    u64 bp[16], w2p[16];
    {
        const float4* br = (const float4*)&g_base[n * HH + hg * 32];
        const float4* wr = (const float4*)&W2[hg * 32];
#pragma unroll
        for (int c = 0; c < 8; c++) {
            float4 bv = br[c], wv = wr[c];
            bp[2 * c]      = pk2(bv.x, bv.y);
            bp[2 * c + 1]  = pk2(bv.z, bv.w);
            w2p[2 * c]     = pk2(wv.x, wv.y);
            w2p[2 * c + 1] = pk2(wv.z, wv.w);
        }
    }
    const float ob2 = 1.0f + b2[0];

    __syncthreads();

#pragma unroll 2
    for (int jj = 0; jj < JT; jj++) {
        const float xj = xs[jj][warp * 4 + nl];
        const float nx = -xj;
        const u64 nx2 = pk2(nx, nx);
        // lane's segment: chunk c at byte offset c*128 + hg*16 within the row
        const float* w1r = &ws[(2 * jj) * HH] + hg * 4;
        const float* per = &ws[(2 * jj + 1) * HH] + hg * 4;
        u64 acc0 = 0ull, acc1 = 0ull;
#pragma unroll
        for (int c = 0; c < 8; c++) {
            float4 wv = *(const float4*)&w1r[c * 32];   // imm offset c*128B
            float4 pv = *(const float4*)&per[c * 32];
            u64 w1a = pk2(wv.x, wv.y), w1b = pk2(wv.z, wv.w);
            u64 pea = pk2(pv.x, pv.y), peb = pk2(pv.z, pv.w);
            u64 v0 = relu2_(add2_(fma2_(nx2, w1a, pea), bp[2 * c]));
            u64 v1 = relu2_(add2_(fma2_(nx2, w1b, peb), bp[2 * c + 1]));
            acc0 = fma2_(v0, w2p[2 * c], acc0);
            acc1 = fma2_(v1, w2p[2 * c + 1], acc1);
        }
        float2 a = unpk(add2_(acc0, acc1));
        float s = a.x + a.y;
        s += __shfl_xor_sync(0xffffffffu, s, 4);
        s += __shfl_xor_sync(0xffffffffu, s, 8);
        s += __shfl_xor_sync(0xffffffffu, s, 16);
        if (hg == 0) out[n * (DD + 1) + 1 + j0 + jj] = xj * (ob2 + s);
    }
}

extern "C" void kernel_launch(void* const* d_in, const int* in_sizes, int n_in,
                              void* d_out, int out_size)
{
    const float* x  = (const float*)d_in[0];
    const float* W1 = (const float*)d_in[1];
    const float* b1 = (const float*)d_in[2];
    const float* W2 = (const float*)d_in[3];
    const float* b2 = (const float*)d_in[4];
    float* out = (float*)d_out;

    // K1: base GEMM + ones column. grid: 64 n-tiles x 4 h-tiles.
    nimo_base_kernel<<<dim3(64, 4), 256>>>(x, W1, b1, out);
    // K2: masked-MLP evaluation. grid: 128 n-tiles x 8 j-tiles.
    nimo_main_kernel<<<dim3(128, 8), 256>>>(x, W1, W2, b2, out);
}

// round 6
// speedup vs baseline: 1.5903x; 1.1848x over previous
#include <cuda_runtime.h>

// Problem constants (fixed by the reference):
//   N=4096 samples, D=128 input dim, P=128 pe dim (== D), H=256 hidden.
#define NN 4096
#define DD 128
#define HH 256

// Scratch: base[n][h] = (x @ W1[:D])[n][h] + b1[h]
__device__ float g_base[NN * HH];

typedef unsigned long long u64;

__device__ __forceinline__ u64 pk2(float x, float y) {
    u64 r; asm("mov.b64 %0, {%1, %2};" : "=l"(r) : "f"(x), "f"(y)); return r;
}
__device__ __forceinline__ u64 fma2_(u64 a, u64 b, u64 c) {
    u64 d; asm("fma.rn.f32x2 %0, %1, %2, %3;" : "=l"(d) : "l"(a), "l"(b), "l"(c)); return d;
}
__device__ __forceinline__ u64 add2_(u64 a, u64 b) {
    u64 d; asm("add.rn.f32x2 %0, %1, %2;" : "=l"(d) : "l"(a), "l"(b)); return d;
}
__device__ __forceinline__ u64 relu2_(u64 a) {
    float x, y;
    asm("mov.b64 {%0, %1}, %2;" : "=f"(x), "=f"(y) : "l"(a));
    x = fmaxf(x, 0.0f); y = fmaxf(y, 0.0f);
    return pk2(x, y);
}
__device__ __forceinline__ float2 unpk(u64 a) {
    float2 v; asm("mov.b64 {%0, %1}, %2;" : "=f"(v.x), "=f"(v.y) : "l"(a)); return v;
}

// ---------------------------------------------------------------------------
// K1: base = x @ W1[:D] + b1   (4096 x 256, K=128), f32x2 accumulators.
// Tiles: 64(n) x 64(h) x 32(k); 256 threads; microtile 4n x 4h (2 packed).
// Also writes the leading ones column of the output (blockIdx.y == 0).
// ---------------------------------------------------------------------------
__global__ __launch_bounds__(256) void nimo_base_kernel(
    const float* __restrict__ x, const float* __restrict__ W1,
    const float* __restrict__ b1, float* __restrict__ out)
{
    __shared__ __align__(16) float xs[32][68];  // [k][n] transposed, padded
    __shared__ __align__(16) float ws[32][68];  // [k][h], padded

    const int tid = threadIdx.x;
    const int n0 = blockIdx.x * 64;
    const int h0 = blockIdx.y * 64;
    const int tx = tid & 15;   // h group -> 4 h (2 packed pairs)
    const int ty = tid >> 4;   // n group -> 4 n

    u64 acc[4][2];
#pragma unroll
    for (int i = 0; i < 4; i++) { acc[i][0] = 0ull; acc[i][1] = 0ull; }

    for (int kt = 0; kt < DD; kt += 32) {
#pragma unroll
        for (int i = 0; i < 8; i++) {           // 64n x 32k
            int e = tid + i * 256;
            int r = e >> 5, k = e & 31;
            xs[k][r] = x[(n0 + r) * DD + kt + k];
        }
#pragma unroll
        for (int i = 0; i < 8; i++) {           // 32k x 64h
            int e = tid + i * 256;
            int k = e >> 6, c = e & 63;
            ws[k][c] = W1[(kt + k) * HH + h0 + c];
        }
        __syncthreads();
#pragma unroll
        for (int kk = 0; kk < 32; kk++) {
            float4 xv = *(const float4*)&xs[kk][ty * 4];
            float4 wv = *(const float4*)&ws[kk][tx * 4];
            u64 wa = pk2(wv.x, wv.y), wb = pk2(wv.z, wv.w);
            u64 x0 = pk2(xv.x, xv.x), x1 = pk2(xv.y, xv.y);
            u64 x2 = pk2(xv.z, xv.z), x3 = pk2(xv.w, xv.w);
            acc[0][0] = fma2_(x0, wa, acc[0][0]); acc[0][1] = fma2_(x0, wb, acc[0][1]);
            acc[1][0] = fma2_(x1, wa, acc[1][0]); acc[1][1] = fma2_(x1, wb, acc[1][1]);
            acc[2][0] = fma2_(x2, wa, acc[2][0]); acc[2][1] = fma2_(x2, wb, acc[2][1]);
            acc[3][0] = fma2_(x3, wa, acc[3][0]); acc[3][1] = fma2_(x3, wb, acc[3][1]);
        }
        __syncthreads();
    }

    float4 bv = *(const float4*)&b1[h0 + tx * 4];
    u64 ba = pk2(bv.x, bv.y), bb = pk2(bv.z, bv.w);
#pragma unroll
    for (int i = 0; i < 4; i++) {
        float2 oa = unpk(add2_(acc[i][0], ba));
        float2 ob = unpk(add2_(acc[i][1], bb));
        float4 o = make_float4(oa.x, oa.y, ob.x, ob.y);
        *(float4*)&g_base[(n0 + ty * 4 + i) * HH + h0 + tx * 4] = o;
    }

    // ones column
    if (blockIdx.y == 0 && tid < 64) out[(n0 + tid) * (DD + 1)] = 1.0f;
}

// ---------------------------------------------------------------------------
// K2: per (n, j):
//   g = sum_h relu(base[n,h] + W1[D+j,h] - x[n,j]*W1[j,h]) * W2[h]
//   out[n, 1+j] = x[n,j] * (1 + b2 + g)
//
// Full 32-lane h-split: lane l owns h-chunks {4l..4l+3} and {128+4l..128+4l+3}
// (8 h). Warp owns 8 n. Register-persistent: base[8n x 8h] (32 u64) and
// W2[8h] (4 u64). Per j, the ONLY memory traffic is 4 perfectly-coalesced
// LDG.128 (W1 row + pe row, zero duplication -> L1-hot, 16 wavefronts per
// 2048 elements) plus 8 lane-uniform LDS of x from a staged tile.
// Reduction: warp-private padded smem transpose (conflict-free STS/LDS,
// __syncwarp only) -> 4-lane quads finish with 2 shfl_xor.
// Block = 256 thr (8 warps, 64 n); grid = (64 n-tiles) x (4 j-tiles of 32).
// ---------------------------------------------------------------------------
__global__ __launch_bounds__(256, 2) void nimo_main_kernel(
    const float* __restrict__ x, const float* __restrict__ W1,
    const float* __restrict__ W2, const float* __restrict__ b2,
    float* __restrict__ out)
{
    __shared__ float xs[64][33];         // staged x tile [n'][j'], padded
    __shared__ float rbuf[8][8][33];     // per-warp reduce buffer [warp][n'][lane]

    const int tid  = threadIdx.x;
    const int lane = tid & 31;
    const int warp = tid >> 5;
    const int n0   = blockIdx.x * 64;
    const int j0   = blockIdx.y * 32;
    const int nb   = n0 + warp * 8;      // warp's first n

    // ---- stage x tile: xs[n'][j'] (coalesced) ----
#pragma unroll
    for (int i = 0; i < 8; i++) {
        int e = tid + i * 256;
        int r = e >> 5, c = e & 31;
        xs[r][c] = x[(n0 + r) * DD + j0 + c];
    }

    // ---- persistent registers: base[8n x lane's 8h] and W2[lane's 8h] ----
    // lane's h-chunks: chunk A = l (floats 4l..4l+3), chunk B = 32+l (floats 128+4l..)
    u64 bp[8][4], w2p[4];
    {
        const float4* w2r = (const float4*)W2;
        float4 wa = w2r[lane], wb = w2r[32 + lane];
        w2p[0] = pk2(wa.x, wa.y); w2p[1] = pk2(wa.z, wa.w);
        w2p[2] = pk2(wb.x, wb.y); w2p[3] = pk2(wb.z, wb.w);
#pragma unroll
        for (int i = 0; i < 8; i++) {
            const float4* br = (const float4*)&g_base[(nb + i) * HH];
            float4 ba = br[lane], bb = br[32 + lane];
            bp[i][0] = pk2(ba.x, ba.y); bp[i][1] = pk2(ba.z, ba.w);
            bp[i][2] = pk2(bb.x, bb.y); bp[i][3] = pk2(bb.z, bb.w);
        }
    }
    const float ob2 = 1.0f + b2[0];
    const int nred = lane >> 2;   // n' this lane reduces
    const int mred = lane & 3;    // quad sub-index

    __syncthreads();

#pragma unroll 1
    for (int jj = 0; jj < 32; jj++) {
        const int j = j0 + jj;
        // coalesced weight loads: W1[j] row + pe row = W1[D+j]
        const float4* w1r = (const float4*)&W1[j * HH];
        const float4* per = (const float4*)&W1[(DD + j) * HH];
        float4 wa = w1r[lane], wb = w1r[32 + lane];
        float4 pa = per[lane], pb = per[32 + lane];
        u64 w1p0 = pk2(wa.x, wa.y), w1p1 = pk2(wa.z, wa.w);
        u64 w1p2 = pk2(wb.x, wb.y), w1p3 = pk2(wb.z, wb.w);
        u64 pep0 = pk2(pa.x, pa.y), pep1 = pk2(pa.z, pa.w);
        u64 pep2 = pk2(pb.x, pb.y), pep3 = pk2(pb.z, pb.w);

#pragma unroll
        for (int i = 0; i < 8; i++) {
            const float xj = xs[warp * 8 + i][jj];   // lane-uniform LDS
            const u64 nx2 = pk2(-xj, -xj);
            u64 a0, a1;
            a0 = fma2_(relu2_(add2_(fma2_(nx2, w1p0, pep0), bp[i][0])), w2p[0], 0ull);
            a1 = fma2_(relu2_(add2_(fma2_(nx2, w1p1, pep1), bp[i][1])), w2p[1], 0ull);
            a0 = fma2_(relu2_(add2_(fma2_(nx2, w1p2, pep2), bp[i][2])), w2p[2], a0);
            a1 = fma2_(relu2_(add2_(fma2_(nx2, w1p3, pep3), bp[i][3])), w2p[3], a1);
            float2 t = unpk(add2_(a0, a1));
            rbuf[warp][i][lane] = t.x + t.y;         // conflict-free STS
        }
        __syncwarp();
        // transpose-reduce: lane -> (n' = lane>>2, reads 8 of 32 partials)
        {
            const float* rr = &rbuf[warp][nred][mred * 8];
            float s = rr[0] + rr[1] + rr[2] + rr[3] + rr[4] + rr[5] + rr[6] + rr[7];
            s += __shfl_xor_sync(0xffffffffu, s, 1);
            s += __shfl_xor_sync(0xffffffffu, s, 2);
            if (mred == 0) {
                const float xj = xs[warp * 8 + nred][jj];
                out[(nb + nred) * (DD + 1) + 1 + j] = xj * (ob2 + s);
            }
        }
        __syncwarp();
    }
}

extern "C" void kernel_launch(void* const* d_in, const int* in_sizes, int n_in,
                              void* d_out, int out_size)
{
    const float* x  = (const float*)d_in[0];
    const float* W1 = (const float*)d_in[1];
    const float* b1 = (const float*)d_in[2];
    const float* W2 = (const float*)d_in[3];
    const float* b2 = (const float*)d_in[4];
    float* out = (float*)d_out;

    // K1: base GEMM + ones column. grid: 64 n-tiles x 4 h-tiles.
    nimo_base_kernel<<<dim3(64, 4), 256>>>(x, W1, b1, out);
    // K2: masked-MLP evaluation. grid: 64 n-tiles x 4 j-tiles of 32.
    nimo_main_kernel<<<dim3(64, 4), 256>>>(x, W1, W2, b2, out);
}

// round 7
// speedup vs baseline: 1.5993x; 1.0057x over previous
#include <cuda_runtime.h>

// Problem constants (fixed by the reference):
//   N=4096 samples, D=128 input dim, P=128 pe dim (== D), H=256 hidden.
#define NN 4096
#define DD 128
#define HH 256

// Scratch: base[n][h] = (x @ W1[:D])[n][h] + b1[h]
__device__ float g_base[NN * HH];

typedef unsigned long long u64;

__device__ __forceinline__ u64 pk2(float x, float y) {
    u64 r; asm("mov.b64 %0, {%1, %2};" : "=l"(r) : "f"(x), "f"(y)); return r;
}
__device__ __forceinline__ u64 fma2_(u64 a, u64 b, u64 c) {
    u64 d; asm("fma.rn.f32x2 %0, %1, %2, %3;" : "=l"(d) : "l"(a), "l"(b), "l"(c)); return d;
}
__device__ __forceinline__ u64 add2_(u64 a, u64 b) {
    u64 d; asm("add.rn.f32x2 %0, %1, %2;" : "=l"(d) : "l"(a), "l"(b)); return d;
}
__device__ __forceinline__ u64 relu2_(u64 a) {
    float x, y;
    asm("mov.b64 {%0, %1}, %2;" : "=f"(x), "=f"(y) : "l"(a));
    x = fmaxf(x, 0.0f); y = fmaxf(y, 0.0f);
    return pk2(x, y);
}
__device__ __forceinline__ float2 unpk(u64 a) {
    float2 v; asm("mov.b64 {%0, %1}, %2;" : "=f"(v.x), "=f"(v.y) : "l"(a)); return v;
}

// ---------------------------------------------------------------------------
// K1: base = x @ W1[:D] + b1   (4096 x 256, K=128), f32x2 accumulators.
// Tiles: 64(n) x 64(h) x 32(k); 256 threads; microtile 4n x 4h (2 packed).
// Also writes the leading ones column of the output (blockIdx.y == 0).
// ---------------------------------------------------------------------------
__global__ __launch_bounds__(256) void nimo_base_kernel(
    const float* __restrict__ x, const float* __restrict__ W1,
    const float* __restrict__ b1, float* __restrict__ out)
{
    __shared__ __align__(16) float xs[32][68];  // [k][n] transposed, padded
    __shared__ __align__(16) float ws[32][68];  // [k][h], padded

    const int tid = threadIdx.x;
    const int n0 = blockIdx.x * 64;
    const int h0 = blockIdx.y * 64;
    const int tx = tid & 15;   // h group -> 4 h (2 packed pairs)
    const int ty = tid >> 4;   // n group -> 4 n

    u64 acc[4][2];
#pragma unroll
    for (int i = 0; i < 4; i++) { acc[i][0] = 0ull; acc[i][1] = 0ull; }

    for (int kt = 0; kt < DD; kt += 32) {
#pragma unroll
        for (int i = 0; i < 8; i++) {           // 64n x 32k
            int e = tid + i * 256;
            int r = e >> 5, k = e & 31;
            xs[k][r] = x[(n0 + r) * DD + kt + k];
        }
#pragma unroll
        for (int i = 0; i < 8; i++) {           // 32k x 64h
            int e = tid + i * 256;
            int k = e >> 6, c = e & 63;
            ws[k][c] = W1[(kt + k) * HH + h0 + c];
        }
        __syncthreads();
#pragma unroll
        for (int kk = 0; kk < 32; kk++) {
            float4 xv = *(const float4*)&xs[kk][ty * 4];
            float4 wv = *(const float4*)&ws[kk][tx * 4];
            u64 wa = pk2(wv.x, wv.y), wb = pk2(wv.z, wv.w);
            u64 x0 = pk2(xv.x, xv.x), x1 = pk2(xv.y, xv.y);
            u64 x2 = pk2(xv.z, xv.z), x3 = pk2(xv.w, xv.w);
            acc[0][0] = fma2_(x0, wa, acc[0][0]); acc[0][1] = fma2_(x0, wb, acc[0][1]);
            acc[1][0] = fma2_(x1, wa, acc[1][0]); acc[1][1] = fma2_(x1, wb, acc[1][1]);
            acc[2][0] = fma2_(x2, wa, acc[2][0]); acc[2][1] = fma2_(x2, wb, acc[2][1]);
            acc[3][0] = fma2_(x3, wa, acc[3][0]); acc[3][1] = fma2_(x3, wb, acc[3][1]);
        }
        __syncthreads();
    }

    float4 bv = *(const float4*)&b1[h0 + tx * 4];
    u64 ba = pk2(bv.x, bv.y), bb = pk2(bv.z, bv.w);
#pragma unroll
    for (int i = 0; i < 4; i++) {
        float2 oa = unpk(add2_(acc[i][0], ba));
        float2 ob = unpk(add2_(acc[i][1], bb));
        float4 o = make_float4(oa.x, oa.y, ob.x, ob.y);
        *(float4*)&g_base[(n0 + ty * 4 + i) * HH + h0 + tx * 4] = o;
    }

    // ones column
    if (blockIdx.y == 0 && tid < 64) out[(n0 + tid) * (DD + 1)] = 1.0f;
}

// ---------------------------------------------------------------------------
// K2: per (n, j):
//   g = sum_h relu(base[n,h] + W1[D+j,h] - x[n,j]*W1[j,h]) * W2[h]
//   out[n, 1+j] = x[n,j] * (1 + b2 + g)
//
// Full 32-lane h-split: lane l owns h-chunks {4l..4l+3} and {128+4l..131+4l}.
// Warp owns 8 n; base[8n x 8h] (32 u64) and W2[8h] register-persistent.
// Per j: the ONLY loads are 4 coalesced LDG.128 (W1 row + pe row, zero
// duplication, L1-hot) -- DOUBLE-BUFFERED so j+1's loads overlap j's math --
// plus 8 lane-uniform LDS of staged x.
// Reduction: value-splitting shuffle tree (9 shfl, no smem, no syncwarp);
// lane group v = lane>>2 ends with the sum for n = nb + v.
// Block = 128 thr (4 warps, 32 n), 4 CTAs/SM; grid = (128 n-tiles) x (4 j-tiles).
// ---------------------------------------------------------------------------
__global__ __launch_bounds__(128, 4) void nimo_main_kernel(
    const float* __restrict__ x, const float* __restrict__ W1,
    const float* __restrict__ W2, const float* __restrict__ b2,
    float* __restrict__ out)
{
    __shared__ float xs[32][33];         // staged x tile [n'][j'], padded

    const int tid  = threadIdx.x;
    const int lane = tid & 31;
    const int warp = tid >> 5;
    const int n0   = blockIdx.x * 32;
    const int j0   = blockIdx.y * 32;
    const int nb   = n0 + warp * 8;      // warp's first n

    // ---- stage x tile: xs[n'][j'] (coalesced) ----
#pragma unroll
    for (int i = 0; i < 8; i++) {
        int e = tid + i * 128;
        int r = e >> 5, c = e & 31;
        xs[r][c] = x[(n0 + r) * DD + j0 + c];
    }

    // ---- persistent registers: base[8n x lane's 8h] and W2[lane's 8h] ----
    u64 bp[8][4], w2p[4];
    {
        const float4* w2r = (const float4*)W2;
        float4 wa = w2r[lane], wb = w2r[32 + lane];
        w2p[0] = pk2(wa.x, wa.y); w2p[1] = pk2(wa.z, wa.w);
        w2p[2] = pk2(wb.x, wb.y); w2p[3] = pk2(wb.z, wb.w);
#pragma unroll
        for (int i = 0; i < 8; i++) {
            const float4* br = (const float4*)&g_base[(nb + i) * HH];
            float4 ba = br[lane], bb = br[32 + lane];
            bp[i][0] = pk2(ba.x, ba.y); bp[i][1] = pk2(ba.z, ba.w);
            bp[i][2] = pk2(bb.x, bb.y); bp[i][3] = pk2(bb.z, bb.w);
        }
    }
    const float ob2 = 1.0f + b2[0];
    const bool h16 = (lane & 16) != 0;
    const bool h8  = (lane & 8) != 0;
    const bool h4  = (lane & 4) != 0;

    __syncthreads();

    // ---- prefetch weights for j0 ----
    float4 fwa, fwb, fpa, fpb;
    {
        const float4* w1r = (const float4*)&W1[j0 * HH];
        const float4* per = (const float4*)&W1[(DD + j0) * HH];
        fwa = w1r[lane]; fwb = w1r[32 + lane];
        fpa = per[lane]; fpb = per[32 + lane];
    }

#pragma unroll 1
    for (int jj = 0; jj < 32; jj++) {
        const int j = j0 + jj;
        // pack current weights
        u64 w1p0 = pk2(fwa.x, fwa.y), w1p1 = pk2(fwa.z, fwa.w);
        u64 w1p2 = pk2(fwb.x, fwb.y), w1p3 = pk2(fwb.z, fwb.w);
        u64 pep0 = pk2(fpa.x, fpa.y), pep1 = pk2(fpa.z, fpa.w);
        u64 pep2 = pk2(fpb.x, fpb.y), pep3 = pk2(fpb.z, fpb.w);
        // prefetch next j (overlaps the math below)
        if (jj < 31) {
            const float4* nw = (const float4*)&W1[(j + 1) * HH];
            const float4* np = (const float4*)&W1[(DD + j + 1) * HH];
            fwa = nw[lane]; fwb = nw[32 + lane];
            fpa = np[lane]; fpb = np[32 + lane];
        }

        float s[8];
#pragma unroll
        for (int i = 0; i < 8; i++) {
            const float xj = xs[warp * 8 + i][jj];   // lane-uniform LDS
            const u64 nx2 = pk2(-xj, -xj);
            u64 a0, a1;
            a0 = fma2_(relu2_(add2_(fma2_(nx2, w1p0, pep0), bp[i][0])), w2p[0], 0ull);
            a1 = fma2_(relu2_(add2_(fma2_(nx2, w1p1, pep1), bp[i][1])), w2p[1], 0ull);
            a0 = fma2_(relu2_(add2_(fma2_(nx2, w1p2, pep2), bp[i][2])), w2p[2], a0);
            a1 = fma2_(relu2_(add2_(fma2_(nx2, w1p3, pep3), bp[i][3])), w2p[3], a1);
            float2 t = unpk(add2_(a0, a1));
            s[i] = t.x + t.y;
        }

        // ---- value-splitting shuffle reduction: 8 vals -> 1 per lane ----
        // level 1 (xor 16): keep 4, send 4
#pragma unroll
        for (int k = 0; k < 4; k++) {
            float snd = h16 ? s[k] : s[k + 4];
            float kp  = h16 ? s[k + 4] : s[k];
            s[k] = kp + __shfl_xor_sync(0xffffffffu, snd, 16);
        }
        // level 2 (xor 8): keep 2, send 2
#pragma unroll
        for (int k = 0; k < 2; k++) {
            float snd = h8 ? s[k] : s[k + 2];
            float kp  = h8 ? s[k + 2] : s[k];
            s[k] = kp + __shfl_xor_sync(0xffffffffu, snd, 8);
        }
        // level 3 (xor 4): keep 1, send 1
        {
            float snd = h4 ? s[0] : s[1];
            float kp  = h4 ? s[1] : s[0];
            s[0] = kp + __shfl_xor_sync(0xffffffffu, snd, 4);
        }
        // levels 4-5: plain butterfly within 4-lane group
        s[0] += __shfl_xor_sync(0xffffffffu, s[0], 2);
        s[0] += __shfl_xor_sync(0xffffffffu, s[0], 1);

        // lane 4v holds the full sum for n = nb + v
        if ((lane & 3) == 0) {
            const int v = lane >> 2;
            const float xj = xs[warp * 8 + v][jj];
            out[(nb + v) * (DD + 1) + 1 + j] = xj * (ob2 + s[0]);
        }
    }
}

extern "C" void kernel_launch(void* const* d_in, const int* in_sizes, int n_in,
                              void* d_out, int out_size)
{
    const float* x  = (const float*)d_in[0];
    const float* W1 = (const float*)d_in[1];
    const float* b1 = (const float*)d_in[2];
    const float* W2 = (const float*)d_in[3];
    const float* b2 = (const float*)d_in[4];
    float* out = (float*)d_out;

    // K1: base GEMM + ones column. grid: 64 n-tiles x 4 h-tiles.
    nimo_base_kernel<<<dim3(64, 4), 256>>>(x, W1, b1, out);
    // K2: masked-MLP evaluation. grid: 128 n-tiles x 4 j-tiles of 32.
    nimo_main_kernel<<<dim3(128, 4), 128>>>(x, W1, W2, b2, out);
}